// round 1
// baseline (speedup 1.0000x reference)
#include <cuda_runtime.h>
#include <math.h>

#define BN 8
#define H 480
#define W 640
#define OH 120
#define OW 160
#define CH 128
#define NP 192          // P keypoints
#define NPIX (BN*H*W)

// ---------------- scratch (static device memory; no allocations) ----------------
__device__ float d_pxx[NPIX];
__device__ float d_pyy[NPIX];
__device__ float d_pxy[NPIX];
__device__ float d_sxx[NPIX];
__device__ float d_syy[NPIX];
__device__ float d_sxy[NPIX];
__device__ float d_g[NPIX];
__device__ float d_cellval[BN*256];
__device__ int   d_cellxy[BN*256];
__device__ int   d_selxy[BN*NP];

// ---------------- K1: gradient products (dx*dx, dy*dy, dx*dy) -------------------
__global__ void k_prod(const float* __restrict__ frame) {
    int idx = blockIdx.x * blockDim.x + threadIdx.x;
    if (idx >= NPIX) return;
    int x = idx % W;
    int y = (idx / W) % H;
    int b = idx / (W * H);
    const float* f = frame + (size_t)b * H * W;
    float dx, dy;
    if (x < W - 1) dx = f[y*W + x + 1] - f[y*W + x];
    else           dx = f[y*W + (W-2)] - f[y*W + (W-3)];   // reflect pad of diff
    if (y < H - 1) dy = f[(y+1)*W + x] - f[y*W + x];
    else           dy = f[(H-2)*W + x] - f[(H-3)*W + x];
    d_pxx[idx] = dx * dx;
    d_pyy[idx] = dy * dy;
    d_pxy[idx] = dx * dy;
}

// ---------------- K2: horizontal 7-tap box sum (zero pad) -----------------------
__global__ void k_hsum() {
    int idx = blockIdx.x * blockDim.x + threadIdx.x;
    if (idx >= NPIX) return;
    int x = idx % W;
    int rowbase = idx - x;
    int lo = x - 3; if (lo < 0) lo = 0;
    int hi = x + 3; if (hi > W-1) hi = W-1;
    float sxx = 0.f, syy = 0.f, sxy = 0.f;
    for (int xx = lo; xx <= hi; xx++) {
        sxx += d_pxx[rowbase + xx];
        syy += d_pyy[rowbase + xx];
        sxy += d_pxy[rowbase + xx];
    }
    d_sxx[idx] = sxx; d_syy[idx] = syy; d_sxy[idx] = sxy;
}

// ---------------- K3: vertical 7-tap box sum + harris response ------------------
__global__ void k_vsum() {
    int idx = blockIdx.x * blockDim.x + threadIdx.x;
    if (idx >= NPIX) return;
    int x = idx % W;
    int y = (idx / W) % H;
    int b = idx / (W * H);
    int lo = y - 3; if (lo < 0) lo = 0;
    int hi = y + 3; if (hi > H-1) hi = H-1;
    int base = b * H * W + x;
    float sxx = 0.f, syy = 0.f, sxy = 0.f;
    for (int yy = lo; yy <= hi; yy++) {
        int k = base + yy * W;
        sxx += d_sxx[k]; syy += d_syy[k]; sxy += d_sxy[k];
    }
    float Ixx = sxx / 49.0f, Iyy = syy / 49.0f, Ixy = sxy / 49.0f;
    d_g[idx] = (Ixx * Iyy - Ixy * Ixy) / (Ixx + Iyy + 1e-8f);
}

// ---------------- K4: per-cell argmax (first-index tie break) -------------------
__global__ void k_cellmax() {
    // grid = BN*256 blocks, 256 threads
    int cell = blockIdx.x;
    int b  = cell >> 8;
    int c  = cell & 255;
    int gh = c >> 4, gw = c & 15;
    const float* g = d_g + (size_t)b * H * W;
    int tid = threadIdx.x;
    float bv = -3.402823466e38f;
    int   bi = 0x7FFFFFFF;
    for (int f = tid; f < 1200; f += 256) {       // f = py*40 + px (scan order)
        int py = f / 40, px = f - py * 40;
        float v = g[(gh*30 + py) * W + (gw*40 + px)];
        if (v > bv) { bv = v; bi = f; }           // ascending f per thread -> first idx wins
    }
    __shared__ float sv[256];
    __shared__ int   si[256];
    sv[tid] = bv; si[tid] = bi;
    __syncthreads();
    for (int s = 128; s > 0; s >>= 1) {
        if (tid < s) {
            float v2 = sv[tid + s]; int i2 = si[tid + s];
            if (v2 > sv[tid] || (v2 == sv[tid] && i2 < si[tid])) { sv[tid] = v2; si[tid] = i2; }
        }
        __syncthreads();
    }
    if (tid == 0) {
        int f = si[0];
        int py = f / 40, px = f - py * 40;
        d_cellval[cell] = sv[0];
        d_cellxy[cell]  = ((gh*30 + py) << 16) | (gw*40 + px);
    }
}

// ---------------- K5: top-192 by rank count (stable, matches lax.top_k) ---------
__global__ void k_topk(float* __restrict__ out_coords) {
    // grid = BN blocks, 256 threads
    __shared__ float sv[256];
    __shared__ int   sxy[256];
    int b = blockIdx.x, i = threadIdx.x;
    sv[i]  = d_cellval[b*256 + i];
    sxy[i] = d_cellxy[b*256 + i];
    __syncthreads();
    float v = sv[i];
    int rank = 0;
    #pragma unroll 8
    for (int j = 0; j < 256; j++) {
        float vj = sv[j];
        rank += (vj > v) || (vj == v && j < i);
    }
    if (rank < NP) {
        int xy = sxy[i];
        int x = xy & 0xFFFF, y = xy >> 16;
        out_coords[((size_t)b*NP + rank)*2 + 0] = (float)x;
        out_coords[((size_t)b*NP + rank)*2 + 1] = (float)y;
        d_selxy[b*NP + rank] = xy;
    }
}

// ---------------- K6: dense fmap conv (1->128ch, 7x7, stride4, pad3) + relu -----
// grid (5, 120, 8), block 64 threads; thread t computes channels 2t, 2t+1 for 32 ox.
__global__ __launch_bounds__(64) void k_conv(
    const float* __restrict__ frame,
    const float* __restrict__ wf,
    const float* __restrict__ bf,
    float* __restrict__ fmap)
{
    __shared__ float s_in[7][132];
    int ox0 = blockIdx.x * 32;
    int oy  = blockIdx.y;
    int b   = blockIdx.z;
    const float* f = frame + (size_t)b * H * W;
    int row0 = oy * 4 - 3, col0 = ox0 * 4 - 3;
    for (int i = threadIdx.x; i < 7 * 131; i += 64) {
        int r = i / 131, cc = i - r * 131;
        int yy = row0 + r, xx = col0 + cc;
        s_in[r][cc] = (yy >= 0 && yy < H && xx >= 0 && xx < W) ? f[yy*W + xx] : 0.f;
    }
    int c0 = threadIdx.x * 2;
    float w0[49], w1[49];
    #pragma unroll
    for (int i = 0; i < 49; i++) {
        w0[i] = __ldg(wf + c0*49 + i);
        w1[i] = __ldg(wf + c0*49 + 49 + i);
    }
    float b0 = __ldg(bf + c0), b1 = __ldg(bf + c0 + 1);
    __syncthreads();

    float* o0 = fmap + (((size_t)(b*CH + c0) * OH + oy) * OW + ox0);
    float* o1 = o0 + (size_t)OH * OW;
    for (int px = 0; px < 32; px++) {
        float a0 = b0, a1 = b1;
        #pragma unroll
        for (int ky = 0; ky < 7; ky++) {
            #pragma unroll
            for (int kx = 0; kx < 7; kx++) {
                float v = s_in[ky][px*4 + kx];
                a0 = fmaf(v, w0[ky*7 + kx], a0);
                a1 = fmaf(v, w1[ky*7 + kx], a1);
            }
        }
        o0[px] = fmaxf(a0, 0.f);
        o1[px] = fmaxf(a1, 0.f);
    }
}

// ---------------- K7: patches_f — bilinear sample fmap at 49 offsets ------------
// grid BN*NP blocks, 128 threads (one channel each)
__global__ void k_patches_f(const float* __restrict__ fmap, float* __restrict__ out) {
    int bp = blockIdx.x;
    int b  = bp / NP;
    int c  = threadIdx.x;
    int xy = d_selxy[bp];
    float fx = (float)(xy & 0xFFFF) * 0.25f;
    float fy = (float)(xy >> 16)    * 0.25f;
    const float* img = fmap + (size_t)(b*CH + c) * OH * OW;
    float* o = out + ((size_t)bp * CH + c) * 49;
    for (int t = 0; t < 49; t++) {
        int j = t / 7, i2 = t - j * 7;
        float xs = fx + (float)(i2 - 3);
        float ys = fy + (float)(j  - 3);
        float x0f = floorf(xs), y0f = floorf(ys);
        int x0 = (int)x0f, y0 = (int)y0f;
        float wx = xs - x0f, wy = ys - y0f;
        float acc = 0.f;
        {   int xi = x0,   yi = y0;
            if (xi >= 0 && xi < OW && yi >= 0 && yi < OH)
                acc += __ldg(img + yi*OW + xi) * ((1.f-wx)*(1.f-wy)); }
        {   int xi = x0+1, yi = y0;
            if (xi >= 0 && xi < OW && yi >= 0 && yi < OH)
                acc += __ldg(img + yi*OW + xi) * (wx*(1.f-wy)); }
        {   int xi = x0,   yi = y0+1;
            if (xi >= 0 && xi < OW && yi >= 0 && yi < OH)
                acc += __ldg(img + yi*OW + xi) * ((1.f-wx)*wy); }
        {   int xi = x0+1, yi = y0+1;
            if (xi >= 0 && xi < OW && yi >= 0 && yi < OH)
                acc += __ldg(img + yi*OW + xi) * (wx*wy); }
        o[t] = acc;
    }
}

// ---------------- K8: patches_c — on-the-fly imap conv at 4 neighbors -----------
// grid BN*NP blocks, 128 threads (one channel each). Avoids dense imap entirely.
__global__ void k_patches_c(
    const float* __restrict__ frame,
    const float* __restrict__ wc,
    const float* __restrict__ bc,
    float* __restrict__ out)
{
    __shared__ float s_in[121];      // 11x11 frame window
    int bp = blockIdx.x;
    int b  = bp / NP;
    int c  = threadIdx.x;
    int xy = d_selxy[bp];
    float fx = (float)(xy & 0xFFFF) * 0.25f;
    float fy = (float)(xy >> 16)    * 0.25f;
    int x0 = (int)floorf(fx);
    int y0 = (int)floorf(fy);
    float wx = fx - (float)x0, wy = fy - (float)y0;

    const float* f = frame + (size_t)b * H * W;
    int row0 = y0 * 4 - 3, col0 = x0 * 4 - 3;
    for (int i = threadIdx.x; i < 121; i += 128) {
        int r = i / 11, cc = i - r * 11;
        int yy = row0 + r, xx = col0 + cc;
        s_in[i] = (yy >= 0 && yy < H && xx >= 0 && xx < W) ? f[yy*W + xx] : 0.f;
    }
    float wreg[49];
    #pragma unroll
    for (int i = 0; i < 49; i++) wreg[i] = __ldg(wc + c*49 + i);
    float bias = __ldg(bc + c);
    __syncthreads();

    float wts[4] = { (1.f-wx)*(1.f-wy), wx*(1.f-wy), (1.f-wx)*wy, wx*wy };
    float acc = 0.f;
    #pragma unroll
    for (int n = 0; n < 4; n++) {
        int dxn = n & 1, dyn = n >> 1;
        int xi = x0 + dxn, yi = y0 + dyn;
        if (xi < OW && yi < OH) {                  // xi,yi >= 0 always (coords >= 0)
            float v = bias;
            #pragma unroll
            for (int ky = 0; ky < 7; ky++)
                #pragma unroll
                for (int kx = 0; kx < 7; kx++)
                    v = fmaf(s_in[(dyn*4 + ky)*11 + (dxn*4 + kx)], wreg[ky*7 + kx], v);
            v = fmaxf(v, 0.f);
            acc += v * wts[n];
        }
    }
    out[(size_t)bp * CH + c] = acc;
}

// ---------------- launch ---------------------------------------------------------
extern "C" void kernel_launch(void* const* d_in, const int* in_sizes, int n_in,
                              void* d_out, int out_size) {
    const float* frame = (const float*)d_in[0];
    const float* w_f   = (const float*)d_in[1];
    const float* b_f   = (const float*)d_in[2];
    const float* w_c   = (const float*)d_in[3];
    const float* b_c   = (const float*)d_in[4];

    float* out        = (float*)d_out;
    float* out_coords = out;                                   // 8*192*2      = 3072
    float* out_pf     = out + 3072;                            // 8*192*128*49 = 9633792
    float* out_pc     = out + 3072 + 9633792;                  // 8*192*128    = 196608
    float* out_fmap   = out + 3072 + 9633792 + 196608;         // 8*128*120*160

    int nblk = (NPIX + 255) / 256;
    k_prod <<<nblk, 256>>>(frame);
    k_hsum <<<nblk, 256>>>();
    k_vsum <<<nblk, 256>>>();
    k_cellmax<<<BN*256, 256>>>();
    k_topk <<<BN, 256>>>(out_coords);

    dim3 gconv(OW/32, OH, BN);
    k_conv<<<gconv, 64>>>(frame, w_f, b_f, out_fmap);

    k_patches_f<<<BN*NP, 128>>>(out_fmap, out_pf);
    k_patches_c<<<BN*NP, 128>>>(frame, w_c, b_c, out_pc);
}

// round 2
// speedup vs baseline: 1.4572x; 1.4572x over previous
#include <cuda_runtime.h>
#include <math.h>

#define BN 8
#define H 480
#define W 640
#define OH 120
#define OW 160
#define CH 128
#define NP 192
#define NPIX (BN*H*W)

// ---------------- scratch (static device memory; no allocations) ----------------
__device__ float d_sxx[NPIX];
__device__ float d_syy[NPIX];
__device__ float d_sxy[NPIX];
__device__ float d_g[NPIX];
__device__ float d_cellval[BN*256];
__device__ int   d_cellxy[BN*256];
__device__ int   d_selxy[BN*NP];

// ---------------- K1: fused gradient products + horizontal 7-tap box sum --------
__global__ void k_prodsum(const float* __restrict__ frame) {
    int idx = blockIdx.x * blockDim.x + threadIdx.x;
    if (idx >= NPIX) return;
    int x = idx % W;
    int y = (idx / W) % H;
    int b = idx / (W * H);
    const float* f = frame + (size_t)b * H * W;
    const float* rowc = f + (size_t)y * W;
    const float* rown = (y < H - 1) ? rowc + W : 0;   // next row for dy
    int lo = x - 3; if (lo < 0) lo = 0;
    int hi = x + 3; if (hi > W - 1) hi = W - 1;
    float dy_edge_a = 0.f, dy_edge_b = 0.f;
    const float* rA = 0; const float* rB = 0;
    if (y < H - 1) { rA = rown; rB = rowc; }
    else           { rA = f + (size_t)(H-2)*W; rB = f + (size_t)(H-3)*W; }
    (void)dy_edge_a; (void)dy_edge_b;
    float sxx = 0.f, syy = 0.f, sxy = 0.f;
    #pragma unroll 7
    for (int xx = lo; xx <= hi; xx++) {
        float c = __ldg(rowc + xx);
        float dx;
        if (xx < W - 1) dx = __ldg(rowc + xx + 1) - c;
        else            dx = __ldg(rowc + (W-2)) - __ldg(rowc + (W-3));
        float dyv = __ldg(rA + xx) - ((y < H - 1) ? c : __ldg(rB + xx));
        sxx = fmaf(dx, dx, sxx);
        syy = fmaf(dyv, dyv, syy);
        sxy = fmaf(dx, dyv, sxy);
    }
    d_sxx[idx] = sxx; d_syy[idx] = syy; d_sxy[idx] = sxy;
}

// ---------------- K2: vertical 7-tap box sum + harris response ------------------
__global__ void k_vsum() {
    int idx = blockIdx.x * blockDim.x + threadIdx.x;
    if (idx >= NPIX) return;
    int x = idx % W;
    int y = (idx / W) % H;
    int b = idx / (W * H);
    int lo = y - 3; if (lo < 0) lo = 0;
    int hi = y + 3; if (hi > H-1) hi = H-1;
    int base = b * H * W + x;
    float sxx = 0.f, syy = 0.f, sxy = 0.f;
    for (int yy = lo; yy <= hi; yy++) {
        int k = base + yy * W;
        sxx += d_sxx[k]; syy += d_syy[k]; sxy += d_sxy[k];
    }
    float Ixx = sxx / 49.0f, Iyy = syy / 49.0f, Ixy = sxy / 49.0f;
    d_g[idx] = (Ixx * Iyy - Ixy * Ixy) / (Ixx + Iyy + 1e-8f);
}

// ---------------- K3: per-cell argmax (first-index tie break) -------------------
__global__ void k_cellmax() {
    int cell = blockIdx.x;
    int b  = cell >> 8;
    int c  = cell & 255;
    int gh = c >> 4, gw = c & 15;
    const float* g = d_g + (size_t)b * H * W;
    int tid = threadIdx.x;
    float bv = -3.402823466e38f;
    int   bi = 0x7FFFFFFF;
    for (int f = tid; f < 1200; f += 256) {
        int py = f / 40, px = f - py * 40;
        float v = g[(gh*30 + py) * W + (gw*40 + px)];
        if (v > bv) { bv = v; bi = f; }
    }
    __shared__ float sv[256];
    __shared__ int   si[256];
    sv[tid] = bv; si[tid] = bi;
    __syncthreads();
    for (int s = 128; s > 0; s >>= 1) {
        if (tid < s) {
            float v2 = sv[tid + s]; int i2 = si[tid + s];
            if (v2 > sv[tid] || (v2 == sv[tid] && i2 < si[tid])) { sv[tid] = v2; si[tid] = i2; }
        }
        __syncthreads();
    }
    if (tid == 0) {
        int f = si[0];
        int py = f / 40, px = f - py * 40;
        d_cellval[cell] = sv[0];
        d_cellxy[cell]  = ((gh*30 + py) << 16) | (gw*40 + px);
    }
}

// ---------------- K4: top-192 by rank count (stable, matches lax.top_k) ---------
__global__ void k_topk(float* __restrict__ out_coords) {
    __shared__ float sv[256];
    __shared__ int   sxy[256];
    int b = blockIdx.x, i = threadIdx.x;
    sv[i]  = d_cellval[b*256 + i];
    sxy[i] = d_cellxy[b*256 + i];
    __syncthreads();
    float v = sv[i];
    int rank = 0;
    #pragma unroll 8
    for (int j = 0; j < 256; j++) {
        float vj = sv[j];
        rank += (vj > v) || (vj == v && j < i);
    }
    if (rank < NP) {
        int xy = sxy[i];
        int x = xy & 0xFFFF, y = xy >> 16;
        out_coords[((size_t)b*NP + rank)*2 + 0] = (float)x;
        out_coords[((size_t)b*NP + rank)*2 + 1] = (float)y;
        d_selxy[b*NP + rank] = xy;
    }
}

// ---------------- K5: dense fmap conv (1->128ch, 7x7, stride4, pad3) + relu -----
__global__ __launch_bounds__(64) void k_conv(
    const float* __restrict__ frame,
    const float* __restrict__ wf,
    const float* __restrict__ bf,
    float* __restrict__ fmap)
{
    __shared__ float s_in[7][132];
    int ox0 = blockIdx.x * 32;
    int oy  = blockIdx.y;
    int b   = blockIdx.z;
    const float* f = frame + (size_t)b * H * W;
    int row0 = oy * 4 - 3, col0 = ox0 * 4 - 3;
    for (int i = threadIdx.x; i < 7 * 131; i += 64) {
        int r = i / 131, cc = i - r * 131;
        int yy = row0 + r, xx = col0 + cc;
        s_in[r][cc] = (yy >= 0 && yy < H && xx >= 0 && xx < W) ? f[yy*W + xx] : 0.f;
    }
    int c0 = threadIdx.x * 2;
    float w0[49], w1[49];
    #pragma unroll
    for (int i = 0; i < 49; i++) {
        w0[i] = __ldg(wf + c0*49 + i);
        w1[i] = __ldg(wf + c0*49 + 49 + i);
    }
    float b0 = __ldg(bf + c0), b1 = __ldg(bf + c0 + 1);
    __syncthreads();

    float* o0 = fmap + (((size_t)(b*CH + c0) * OH + oy) * OW + ox0);
    float* o1 = o0 + (size_t)OH * OW;
    for (int px = 0; px < 32; px++) {
        float a0 = b0, a1 = b1;
        #pragma unroll
        for (int ky = 0; ky < 7; ky++) {
            #pragma unroll
            for (int kx = 0; kx < 7; kx++) {
                float v = s_in[ky][px*4 + kx];
                a0 = fmaf(v, w0[ky*7 + kx], a0);
                a1 = fmaf(v, w1[ky*7 + kx], a1);
            }
        }
        o0[px] = fmaxf(a0, 0.f);
        o1[px] = fmaxf(a1, 0.f);
    }
}

// ---------------- K6: patches_f v2 — 8x8 window gather + register bilinear ------
// One block per (b,p). 128 threads. Integer tap offsets => wx,wy shared across
// all 49 taps, so each channel needs only its 8x8 integer-grid window.
__global__ __launch_bounds__(128) void k_patches_f(
    const float* __restrict__ fmap, float* __restrict__ out)
{
    __shared__ float s[128 * 65];           // [c][65] padded; reused for output
    int bp = blockIdx.x;
    int b  = bp / NP;
    int xy = d_selxy[bp];
    float fx = (float)(xy & 0xFFFF) * 0.25f;
    float fy = (float)(xy >> 16)    * 0.25f;
    int x0 = (int)floorf(fx);
    int y0 = (int)floorf(fy);
    float wx = fx - (float)x0, wy = fy - (float)y0;
    int gx0 = x0 - 3, gy0 = y0 - 3;

    const float* base = fmap + (size_t)b * CH * OH * OW;

    // cooperative load: warp lanes map to (yy,xx) of the 8x8 window, loop channels
    int warp = threadIdx.x >> 5, lane = threadIdx.x & 31;
    int yy = lane >> 3, xx = lane & 7;
    int gx = gx0 + xx;
    bool okx = (gx >= 0 && gx < OW);
    int gya = gy0 + yy;          // rows 0..3
    int gyb = gya + 4;           // rows 4..7
    bool oka = okx && (gya >= 0 && gya < OH);
    bool okb = okx && (gyb < OH);           // gyb >= 1 always
    #pragma unroll 4
    for (int k = 0; k < 32; k++) {
        int c = warp * 32 + k;
        const float* img = base + (size_t)c * OH * OW;
        float va = oka ? __ldg(img + gya*OW + gx) : 0.f;
        float vb = okb ? __ldg(img + gyb*OW + gx) : 0.f;
        s[c * 65 + (yy*8 + xx)]       = va;
        s[c * 65 + ((yy+4)*8 + xx)]   = vb;
    }
    __syncthreads();

    // pull own channel's 64 values into registers
    int c = threadIdx.x;
    float reg[64];
    #pragma unroll
    for (int k = 0; k < 64; k++) reg[k] = s[c * 65 + k];
    __syncthreads();   // everyone has regs; safe to overwrite s with outputs

    float w00 = (1.f - wx) * (1.f - wy);
    float w10 = wx * (1.f - wy);
    float w01 = (1.f - wx) * wy;
    float w11 = wx * wy;

    #pragma unroll
    for (int j = 0; j < 7; j++) {
        #pragma unroll
        for (int i = 0; i < 7; i++) {
            float acc = reg[j*8 + i]     * w00
                      + reg[j*8 + i + 1] * w10
                      + reg[(j+1)*8 + i]     * w01
                      + reg[(j+1)*8 + i + 1] * w11;
            s[c * 49 + (j*7 + i)] = acc;
        }
    }
    __syncthreads();

    // coalesced copy-out: 128*49 = 6272 floats contiguous
    float* o = out + (size_t)bp * (CH * 49);
    for (int k = threadIdx.x; k < CH * 49; k += 128)
        o[k] = s[k];
}

// ---------------- K7: patches_c — on-the-fly imap conv at 4 neighbors -----------
__global__ void k_patches_c(
    const float* __restrict__ frame,
    const float* __restrict__ wc,
    const float* __restrict__ bc,
    float* __restrict__ out)
{
    __shared__ float s_in[121];
    int bp = blockIdx.x;
    int b  = bp / NP;
    int c  = threadIdx.x;
    int xy = d_selxy[bp];
    float fx = (float)(xy & 0xFFFF) * 0.25f;
    float fy = (float)(xy >> 16)    * 0.25f;
    int x0 = (int)floorf(fx);
    int y0 = (int)floorf(fy);
    float wx = fx - (float)x0, wy = fy - (float)y0;

    const float* f = frame + (size_t)b * H * W;
    int row0 = y0 * 4 - 3, col0 = x0 * 4 - 3;
    for (int i = threadIdx.x; i < 121; i += 128) {
        int r = i / 11, cc = i - r * 11;
        int yyy = row0 + r, xxx = col0 + cc;
        s_in[i] = (yyy >= 0 && yyy < H && xxx >= 0 && xxx < W) ? f[yyy*W + xxx] : 0.f;
    }
    float wreg[49];
    #pragma unroll
    for (int i = 0; i < 49; i++) wreg[i] = __ldg(wc + c*49 + i);
    float bias = __ldg(bc + c);
    __syncthreads();

    float wts[4] = { (1.f-wx)*(1.f-wy), wx*(1.f-wy), (1.f-wx)*wy, wx*wy };
    float acc = 0.f;
    #pragma unroll
    for (int n = 0; n < 4; n++) {
        int dxn = n & 1, dyn = n >> 1;
        int xi = x0 + dxn, yi = y0 + dyn;
        if (xi < OW && yi < OH) {
            float v = bias;
            #pragma unroll
            for (int ky = 0; ky < 7; ky++)
                #pragma unroll
                for (int kx = 0; kx < 7; kx++)
                    v = fmaf(s_in[(dyn*4 + ky)*11 + (dxn*4 + kx)], wreg[ky*7 + kx], v);
            v = fmaxf(v, 0.f);
            acc += v * wts[n];
        }
    }
    out[(size_t)bp * CH + c] = acc;
}

// ---------------- launch ---------------------------------------------------------
extern "C" void kernel_launch(void* const* d_in, const int* in_sizes, int n_in,
                              void* d_out, int out_size) {
    const float* frame = (const float*)d_in[0];
    const float* w_f   = (const float*)d_in[1];
    const float* b_f   = (const float*)d_in[2];
    const float* w_c   = (const float*)d_in[3];
    const float* b_c   = (const float*)d_in[4];

    float* out        = (float*)d_out;
    float* out_coords = out;                                   // 8*192*2
    float* out_pf     = out + 3072;                            // 8*192*128*49
    float* out_pc     = out + 3072 + 9633792;                  // 8*192*128
    float* out_fmap   = out + 3072 + 9633792 + 196608;         // 8*128*120*160

    int nblk = (NPIX + 255) / 256;
    k_prodsum<<<nblk, 256>>>(frame);
    k_vsum   <<<nblk, 256>>>();
    k_cellmax<<<BN*256, 256>>>();
    k_topk   <<<BN, 256>>>(out_coords);

    dim3 gconv(OW/32, OH, BN);
    k_conv<<<gconv, 64>>>(frame, w_f, b_f, out_fmap);

    k_patches_f<<<BN*NP, 128>>>(out_fmap, out_pf);
    k_patches_c<<<BN*NP, 128>>>(frame, w_c, b_c, out_pc);
}

// round 3
// speedup vs baseline: 2.0250x; 1.3896x over previous
#include <cuda_runtime.h>
#include <math.h>
#include <float.h>

#define BN 8
#define H 480
#define W 640
#define OH 120
#define OW 160
#define CH 128
#define NP 192

typedef unsigned long long u64;

// ---------------- scratch ----------------
__device__ float d_cellval[BN*256];
__device__ int   d_cellxy[BN*256];
__device__ int   d_selxy[BN*NP];

// ---------------- f32x2 helpers ----------------
__device__ __forceinline__ u64 pack2(float lo, float hi) {
    u64 r; asm("mov.b64 %0, {%1, %2};" : "=l"(r) : "f"(lo), "f"(hi)); return r;
}
__device__ __forceinline__ void unpack2(u64 v, float& lo, float& hi) {
    asm("mov.b64 {%0, %1}, %2;" : "=f"(lo), "=f"(hi) : "l"(v));
}
__device__ __forceinline__ u64 ffma2(u64 a, u64 b, u64 c) {
    u64 d; asm("fma.rn.f32x2 %0, %1, %2, %3;" : "=l"(d) : "l"(a), "l"(b), "l"(c)); return d;
}

// ================= K1: fully fused harris + per-cell argmax =================
// One block per grid cell (30 rows x 40 cols of g). Never materializes g or
// the gradient-product maps: frame window -> products -> hsum -> vsum+harris
// -> cell argmax, all in shared memory.
__global__ __launch_bounds__(256) void k_harris(const float* __restrict__ frame) {
    __shared__ float sf[37][48];                    // frame window (37 x 47 used)
    __shared__ float spxx[36][48], spyy[36][48], spxy[36][48];  // products (36 x 46 used)
    __shared__ float shxx[36][40], shyy[36][40], shxy[36][40];  // horiz sums
    __shared__ float sv[256];
    __shared__ int   si[256];

    int blk = blockIdx.x;
    int b = blk >> 8, cell = blk & 255;
    int gh = cell >> 4, gw = cell & 15;
    int gx0 = gw * 40, gy0 = gh * 30;
    int X0 = gx0 - 3, Y0 = gy0 - 3;
    const float* f = frame + (size_t)b * H * W;
    int tid = threadIdx.x;

    // load frame window (zero outside image; outside values never used for valid px)
    for (int i = tid; i < 37 * 47; i += 256) {
        int r = i / 47, c = i - r * 47;
        int x = X0 + c, y = Y0 + r;
        sf[r][c] = (x >= 0 && x < W && y >= 0 && y < H) ? f[y * W + x] : 0.f;
    }
    __syncthreads();

    // gradient products over the 46x36 region (zero where outside image)
    for (int i = tid; i < 36 * 46; i += 256) {
        int r = i / 46, c = i - r * 46;
        int x = X0 + c, y = Y0 + r;
        float pxx = 0.f, pyy = 0.f, pxy = 0.f;
        if (x >= 0 && x < W && y >= 0 && y < H) {
            float dx = (x < W - 1) ? (sf[r][c+1] - sf[r][c]) : (sf[r][c-1] - sf[r][c-2]);
            float dy = (y < H - 1) ? (sf[r+1][c] - sf[r][c]) : (sf[r-1][c] - sf[r-2][c]);
            pxx = dx * dx; pyy = dy * dy; pxy = dx * dy;
        }
        spxx[r][c] = pxx; spyy[r][c] = pyy; spxy[r][c] = pxy;
    }
    __syncthreads();

    // horizontal 7-tap box sums
    for (int i = tid; i < 36 * 40; i += 256) {
        int r = i / 40, c = i - r * 40;
        float a = 0.f, bb = 0.f, cc = 0.f;
        #pragma unroll
        for (int k = 0; k < 7; k++) {
            a  += spxx[r][c + k];
            bb += spyy[r][c + k];
            cc += spxy[r][c + k];
        }
        shxx[r][c] = a; shyy[r][c] = bb; shxy[r][c] = cc;
    }
    __syncthreads();

    // vertical sums + harris + local argmax (ascending f -> first-index ties)
    float bv = -FLT_MAX;
    int   bi = 0x7FFFFFFF;
    for (int fi = tid; fi < 1200; fi += 256) {
        int py = fi / 40, px = fi - py * 40;
        float a = 0.f, bb = 0.f, cc = 0.f;
        #pragma unroll
        for (int k = 0; k < 7; k++) {
            a  += shxx[py + k][px];
            bb += shyy[py + k][px];
            cc += shxy[py + k][px];
        }
        float Ixx = a / 49.0f, Iyy = bb / 49.0f, Ixy = cc / 49.0f;
        float g = (Ixx * Iyy - Ixy * Ixy) / (Ixx + Iyy + 1e-8f);
        if (g > bv) { bv = g; bi = fi; }
    }
    sv[tid] = bv; si[tid] = bi;
    __syncthreads();
    for (int s = 128; s > 0; s >>= 1) {
        if (tid < s) {
            float v2 = sv[tid + s]; int i2 = si[tid + s];
            if (v2 > sv[tid] || (v2 == sv[tid] && i2 < si[tid])) { sv[tid] = v2; si[tid] = i2; }
        }
        __syncthreads();
    }
    if (tid == 0) {
        int fi = si[0];
        int py = fi / 40, px = fi - py * 40;
        d_cellval[blk] = sv[0];
        d_cellxy[blk]  = ((gy0 + py) << 16) | (gx0 + px);
    }
}

// ================= K2: top-192 by rank count (stable) =================
__global__ void k_topk(float* __restrict__ out_coords) {
    __shared__ float sv[256];
    __shared__ int   sxy[256];
    int b = blockIdx.x, i = threadIdx.x;
    sv[i]  = d_cellval[b*256 + i];
    sxy[i] = d_cellxy[b*256 + i];
    __syncthreads();
    float v = sv[i];
    int rank = 0;
    #pragma unroll 8
    for (int j = 0; j < 256; j++) {
        float vj = sv[j];
        rank += (vj > v) || (vj == v && j < i);
    }
    if (rank < NP) {
        int xy = sxy[i];
        int x = xy & 0xFFFF, y = xy >> 16;
        out_coords[((size_t)b*NP + rank)*2 + 0] = (float)x;
        out_coords[((size_t)b*NP + rank)*2 + 1] = (float)y;
        d_selxy[b*NP + rank] = xy;
    }
}

// ================= K3: dense fmap conv, FFMA2 + coalesced stores =================
// block = 64 threads (2 warps). Warp lanes = channel pairs -> smem v loads are
// warp-uniform broadcasts of duplicated float2 (v,v). Each block: 2 output rows
// x 32 px x 128 ch. Output staged in smem, stored coalesced.
__global__ __launch_bounds__(64) void k_conv(
    const float* __restrict__ frame,
    const float* __restrict__ wf,
    const float* __restrict__ bf,
    float* __restrict__ fmap)
{
    __shared__ u64   sin2[11][132];          // duplicated (v,v); rows for 2 oy
    __shared__ float sout[2][128][33];       // [oyr][ch][px]

    int ox0 = blockIdx.x * 32;
    int oy0 = blockIdx.y * 2;
    int b   = blockIdx.z;
    const float* f = frame + (size_t)b * H * W;
    int row0 = oy0 * 4 - 3, col0 = ox0 * 4 - 3;

    for (int i = threadIdx.x; i < 11 * 131; i += 64) {
        int r = i / 131, c = i - r * 131;
        int y = row0 + r, x = col0 + c;
        float v = (y >= 0 && y < H && x >= 0 && x < W) ? f[y*W + x] : 0.f;
        sin2[r][c] = pack2(v, v);
    }

    // channel pair for this thread: warp0 -> ch 0..63, warp1 -> ch 64..127
    int lane = threadIdx.x & 31;
    int warp = threadIdx.x >> 5;
    int c0 = warp * 64 + lane * 2;

    u64 wreg[49];
    #pragma unroll
    for (int i = 0; i < 49; i++)
        wreg[i] = pack2(__ldg(wf + c0*49 + i), __ldg(wf + (c0+1)*49 + i));
    u64 bias2 = pack2(__ldg(bf + c0), __ldg(bf + c0 + 1));
    __syncthreads();

    #pragma unroll 1
    for (int oyr = 0; oyr < 2; oyr++) {
        #pragma unroll 1
        for (int px = 0; px < 32; px++) {
            u64 acc = bias2;
            #pragma unroll
            for (int ky = 0; ky < 7; ky++) {
                #pragma unroll
                for (int kx = 0; kx < 7; kx++) {
                    acc = ffma2(sin2[oyr*4 + ky][px*4 + kx], wreg[ky*7 + kx], acc);
                }
            }
            float a0, a1; unpack2(acc, a0, a1);
            sout[oyr][c0  ][px] = fmaxf(a0, 0.f);
            sout[oyr][c0+1][px] = fmaxf(a1, 0.f);
        }
    }
    __syncthreads();

    // coalesced store: consecutive threads -> consecutive px
    for (int i = threadIdx.x; i < 2 * 128 * 32; i += 64) {
        int px  = i & 31;
        int ch  = (i >> 5) & 127;
        int oyr = i >> 12;
        fmap[(((size_t)(b*CH + ch)) * OH + (oy0 + oyr)) * OW + ox0 + px] = sout[oyr][ch][px];
    }
}

// ================= K4: patches_f — 8x8 window gather + register bilinear ========
__global__ __launch_bounds__(128) void k_patches_f(
    const float* __restrict__ fmap, float* __restrict__ out)
{
    __shared__ float s[128 * 65];
    int bp = blockIdx.x;
    int b  = bp / NP;
    int xy = d_selxy[bp];
    float fx = (float)(xy & 0xFFFF) * 0.25f;
    float fy = (float)(xy >> 16)    * 0.25f;
    int x0 = (int)floorf(fx);
    int y0 = (int)floorf(fy);
    float wx = fx - (float)x0, wy = fy - (float)y0;
    int gx0 = x0 - 3, gy0 = y0 - 3;

    const float* base = fmap + (size_t)b * CH * OH * OW;

    int warp = threadIdx.x >> 5, lane = threadIdx.x & 31;
    int yy = lane >> 3, xx = lane & 7;
    int gx = gx0 + xx;
    bool okx = (gx >= 0 && gx < OW);
    int gya = gy0 + yy;
    int gyb = gya + 4;
    bool oka = okx && (gya >= 0 && gya < OH);
    bool okb = okx && (gyb < OH);
    #pragma unroll 4
    for (int k = 0; k < 32; k++) {
        int c = warp * 32 + k;
        const float* img = base + (size_t)c * OH * OW;
        float va = oka ? __ldg(img + gya*OW + gx) : 0.f;
        float vb = okb ? __ldg(img + gyb*OW + gx) : 0.f;
        s[c * 65 + (yy*8 + xx)]     = va;
        s[c * 65 + ((yy+4)*8 + xx)] = vb;
    }
    __syncthreads();

    int c = threadIdx.x;
    float reg[64];
    #pragma unroll
    for (int k = 0; k < 64; k++) reg[k] = s[c * 65 + k];
    __syncthreads();

    float w00 = (1.f - wx) * (1.f - wy);
    float w10 = wx * (1.f - wy);
    float w01 = (1.f - wx) * wy;
    float w11 = wx * wy;

    #pragma unroll
    for (int j = 0; j < 7; j++) {
        #pragma unroll
        for (int i = 0; i < 7; i++) {
            float acc = reg[j*8 + i]       * w00
                      + reg[j*8 + i + 1]   * w10
                      + reg[(j+1)*8 + i]   * w01
                      + reg[(j+1)*8 + i+1] * w11;
            s[c * 49 + (j*7 + i)] = acc;
        }
    }
    __syncthreads();

    float* o = out + (size_t)bp * (CH * 49);
    for (int k = threadIdx.x; k < CH * 49; k += 128)
        o[k] = s[k];
}

// ================= K5: patches_c — on-the-fly imap conv at 4 neighbors ==========
__global__ void k_patches_c(
    const float* __restrict__ frame,
    const float* __restrict__ wc,
    const float* __restrict__ bc,
    float* __restrict__ out)
{
    __shared__ float s_in[121];
    int bp = blockIdx.x;
    int b  = bp / NP;
    int c  = threadIdx.x;
    int xy = d_selxy[bp];
    float fx = (float)(xy & 0xFFFF) * 0.25f;
    float fy = (float)(xy >> 16)    * 0.25f;
    int x0 = (int)floorf(fx);
    int y0 = (int)floorf(fy);
    float wx = fx - (float)x0, wy = fy - (float)y0;

    const float* f = frame + (size_t)b * H * W;
    int row0 = y0 * 4 - 3, col0 = x0 * 4 - 3;
    for (int i = threadIdx.x; i < 121; i += 128) {
        int r = i / 11, cc = i - r * 11;
        int yyy = row0 + r, xxx = col0 + cc;
        s_in[i] = (yyy >= 0 && yyy < H && xxx >= 0 && xxx < W) ? f[yyy*W + xxx] : 0.f;
    }
    float wreg[49];
    #pragma unroll
    for (int i = 0; i < 49; i++) wreg[i] = __ldg(wc + c*49 + i);
    float bias = __ldg(bc + c);
    __syncthreads();

    float wts[4] = { (1.f-wx)*(1.f-wy), wx*(1.f-wy), (1.f-wx)*wy, wx*wy };
    float acc = 0.f;
    #pragma unroll
    for (int n = 0; n < 4; n++) {
        int dxn = n & 1, dyn = n >> 1;
        int xi = x0 + dxn, yi = y0 + dyn;
        if (xi < OW && yi < OH) {
            float v = bias;
            #pragma unroll
            for (int ky = 0; ky < 7; ky++)
                #pragma unroll
                for (int kx = 0; kx < 7; kx++)
                    v = fmaf(s_in[(dyn*4 + ky)*11 + (dxn*4 + kx)], wreg[ky*7 + kx], v);
            v = fmaxf(v, 0.f);
            acc += v * wts[n];
        }
    }
    out[(size_t)bp * CH + c] = acc;
}

// ---------------- launch ---------------------------------------------------------
extern "C" void kernel_launch(void* const* d_in, const int* in_sizes, int n_in,
                              void* d_out, int out_size) {
    const float* frame = (const float*)d_in[0];
    const float* w_f   = (const float*)d_in[1];
    const float* b_f   = (const float*)d_in[2];
    const float* w_c   = (const float*)d_in[3];
    const float* b_c   = (const float*)d_in[4];

    float* out        = (float*)d_out;
    float* out_coords = out;                                   // 8*192*2
    float* out_pf     = out + 3072;                            // 8*192*128*49
    float* out_pc     = out + 3072 + 9633792;                  // 8*192*128
    float* out_fmap   = out + 3072 + 9633792 + 196608;         // 8*128*120*160

    k_harris<<<BN*256, 256>>>(frame);
    k_topk  <<<BN, 256>>>(out_coords);

    dim3 gconv(OW/32, OH/2, BN);
    k_conv<<<gconv, 64>>>(frame, w_f, b_f, out_fmap);

    k_patches_f<<<BN*NP, 128>>>(out_fmap, out_pf);
    k_patches_c<<<BN*NP, 128>>>(frame, w_c, b_c, out_pc);
}

// round 4
// speedup vs baseline: 2.5163x; 1.2426x over previous
#include <cuda_runtime.h>
#include <math.h>
#include <float.h>

#define BN 8
#define H 480
#define W 640
#define OH 120
#define OW 160
#define CH 128
#define NP 192

typedef unsigned long long u64;

// ---------------- scratch ----------------
__device__ float d_cellval[BN*256];
__device__ int   d_cellxy[BN*256];
__device__ int   d_selxy[BN*NP];

// ---------------- f32x2 helpers ----------------
__device__ __forceinline__ u64 pack2(float lo, float hi) {
    u64 r; asm("mov.b64 %0, {%1, %2};" : "=l"(r) : "f"(lo), "f"(hi)); return r;
}
__device__ __forceinline__ void unpack2(u64 v, float& lo, float& hi) {
    asm("mov.b64 {%0, %1}, %2;" : "=f"(lo), "=f"(hi) : "l"(v));
}
__device__ __forceinline__ u64 ffma2(u64 a, u64 b, u64 c) {
    u64 d; asm("fma.rn.f32x2 %0, %1, %2, %3;" : "=l"(d) : "l"(a), "l"(b), "l"(c)); return d;
}

// ================= K1: fused harris + per-cell argmax =================
__global__ __launch_bounds__(256) void k_harris(const float* __restrict__ frame) {
    __shared__ float sf[37][48];
    __shared__ float spxx[36][48], spyy[36][48], spxy[36][48];
    __shared__ float shxx[36][40], shyy[36][40], shxy[36][40];
    __shared__ float sv[256];
    __shared__ int   si[256];

    int blk = blockIdx.x;
    int b = blk >> 8, cell = blk & 255;
    int gh = cell >> 4, gw = cell & 15;
    int gx0 = gw * 40, gy0 = gh * 30;
    int X0 = gx0 - 3, Y0 = gy0 - 3;
    const float* f = frame + (size_t)b * H * W;
    int tid = threadIdx.x;

    for (int i = tid; i < 37 * 47; i += 256) {
        int r = i / 47, c = i - r * 47;
        int x = X0 + c, y = Y0 + r;
        sf[r][c] = (x >= 0 && x < W && y >= 0 && y < H) ? f[y * W + x] : 0.f;
    }
    __syncthreads();

    for (int i = tid; i < 36 * 46; i += 256) {
        int r = i / 46, c = i - r * 46;
        int x = X0 + c, y = Y0 + r;
        float pxx = 0.f, pyy = 0.f, pxy = 0.f;
        if (x >= 0 && x < W && y >= 0 && y < H) {
            float dx = (x < W - 1) ? (sf[r][c+1] - sf[r][c]) : (sf[r][c-1] - sf[r][c-2]);
            float dy = (y < H - 1) ? (sf[r+1][c] - sf[r][c]) : (sf[r-1][c] - sf[r-2][c]);
            pxx = dx * dx; pyy = dy * dy; pxy = dx * dy;
        }
        spxx[r][c] = pxx; spyy[r][c] = pyy; spxy[r][c] = pxy;
    }
    __syncthreads();

    for (int i = tid; i < 36 * 40; i += 256) {
        int r = i / 40, c = i - r * 40;
        float a = 0.f, bb = 0.f, cc = 0.f;
        #pragma unroll
        for (int k = 0; k < 7; k++) {
            a  += spxx[r][c + k];
            bb += spyy[r][c + k];
            cc += spxy[r][c + k];
        }
        shxx[r][c] = a; shyy[r][c] = bb; shxy[r][c] = cc;
    }
    __syncthreads();

    float bv = -FLT_MAX;
    int   bi = 0x7FFFFFFF;
    for (int fi = tid; fi < 1200; fi += 256) {
        int py = fi / 40, px = fi - py * 40;
        float a = 0.f, bb = 0.f, cc = 0.f;
        #pragma unroll
        for (int k = 0; k < 7; k++) {
            a  += shxx[py + k][px];
            bb += shyy[py + k][px];
            cc += shxy[py + k][px];
        }
        float Ixx = a / 49.0f, Iyy = bb / 49.0f, Ixy = cc / 49.0f;
        float g = (Ixx * Iyy - Ixy * Ixy) / (Ixx + Iyy + 1e-8f);
        if (g > bv) { bv = g; bi = fi; }
    }
    sv[tid] = bv; si[tid] = bi;
    __syncthreads();
    for (int s = 128; s > 0; s >>= 1) {
        if (tid < s) {
            float v2 = sv[tid + s]; int i2 = si[tid + s];
            if (v2 > sv[tid] || (v2 == sv[tid] && i2 < si[tid])) { sv[tid] = v2; si[tid] = i2; }
        }
        __syncthreads();
    }
    if (tid == 0) {
        int fi = si[0];
        int py = fi / 40, px = fi - py * 40;
        d_cellval[blk] = sv[0];
        d_cellxy[blk]  = ((gy0 + py) << 16) | (gx0 + px);
    }
}

// ================= K2: top-192 by rank count (stable) =================
__global__ void k_topk(float* __restrict__ out_coords) {
    __shared__ float sv[256];
    __shared__ int   sxy[256];
    int b = blockIdx.x, i = threadIdx.x;
    sv[i]  = d_cellval[b*256 + i];
    sxy[i] = d_cellxy[b*256 + i];
    __syncthreads();
    float v = sv[i];
    int rank = 0;
    #pragma unroll 8
    for (int j = 0; j < 256; j++) {
        float vj = sv[j];
        rank += (vj > v) || (vj == v && j < i);
    }
    if (rank < NP) {
        int xy = sxy[i];
        int x = xy & 0xFFFF, y = xy >> 16;
        out_coords[((size_t)b*NP + rank)*2 + 0] = (float)x;
        out_coords[((size_t)b*NP + rank)*2 + 1] = (float)y;
        d_selxy[b*NP + rank] = xy;
    }
}

// ================= K3: conv v4 — FFMA2 + 4-px ILP + single-row staging ==========
__global__ __launch_bounds__(64) void k_conv(
    const float* __restrict__ frame,
    const float* __restrict__ wf,
    const float* __restrict__ bf,
    float* __restrict__ fmap)
{
    __shared__ u64   sin2[11][132];          // duplicated (v,v) for 2 output rows
    __shared__ float sout[128][33];          // one output row at a time

    int ox0 = blockIdx.x * 32;
    int oy0 = blockIdx.y * 2;
    int b   = blockIdx.z;
    const float* f = frame + (size_t)b * H * W;
    int row0 = oy0 * 4 - 3, col0 = ox0 * 4 - 3;

    for (int i = threadIdx.x; i < 11 * 131; i += 64) {
        int r = i / 131, c = i - r * 131;
        int y = row0 + r, x = col0 + c;
        float v = (y >= 0 && y < H && x >= 0 && x < W) ? f[y*W + x] : 0.f;
        sin2[r][c] = pack2(v, v);
    }

    int lane = threadIdx.x & 31;
    int warp = threadIdx.x >> 5;
    int c0 = warp * 64 + lane * 2;

    u64 wreg[49];
    #pragma unroll
    for (int i = 0; i < 49; i++)
        wreg[i] = pack2(__ldg(wf + c0*49 + i), __ldg(wf + (c0+1)*49 + i));
    u64 bias2 = pack2(__ldg(bf + c0), __ldg(bf + c0 + 1));
    __syncthreads();

    #pragma unroll 1
    for (int oyr = 0; oyr < 2; oyr++) {
        #pragma unroll 1
        for (int g = 0; g < 8; g++) {                 // px groups of 4 (ILP)
            u64 a0 = bias2, a1 = bias2, a2 = bias2, a3 = bias2;
            #pragma unroll
            for (int ky = 0; ky < 7; ky++) {
                const u64* rowp = &sin2[oyr*4 + ky][g*16];
                #pragma unroll
                for (int kx = 0; kx < 7; kx++) {
                    u64 w = wreg[ky*7 + kx];
                    a0 = ffma2(rowp[kx],      w, a0);
                    a1 = ffma2(rowp[kx + 4],  w, a1);
                    a2 = ffma2(rowp[kx + 8],  w, a2);
                    a3 = ffma2(rowp[kx + 12], w, a3);
                }
            }
            float v0, v1;
            unpack2(a0, v0, v1); sout[c0][g*4+0] = fmaxf(v0,0.f); sout[c0+1][g*4+0] = fmaxf(v1,0.f);
            unpack2(a1, v0, v1); sout[c0][g*4+1] = fmaxf(v0,0.f); sout[c0+1][g*4+1] = fmaxf(v1,0.f);
            unpack2(a2, v0, v1); sout[c0][g*4+2] = fmaxf(v0,0.f); sout[c0+1][g*4+2] = fmaxf(v1,0.f);
            unpack2(a3, v0, v1); sout[c0][g*4+3] = fmaxf(v0,0.f); sout[c0+1][g*4+3] = fmaxf(v1,0.f);
        }
        __syncthreads();
        for (int i = threadIdx.x; i < 128 * 32; i += 64) {
            int px = i & 31;
            int ch = i >> 5;
            fmap[(((size_t)(b*CH + ch)) * OH + (oy0 + oyr)) * OW + ox0 + px] = sout[ch][px];
        }
        __syncthreads();
    }
}

// ================= K4: patches_f v3 — 64 channels/block =================
__global__ __launch_bounds__(128) void k_patches_f(
    const float* __restrict__ fmap, float* __restrict__ out)
{
    __shared__ float s[64 * 65];            // [c_local][65]; reused for output
    int bp   = blockIdx.x >> 1;
    int half = blockIdx.x & 1;
    int b    = bp / NP;
    int xy = d_selxy[bp];
    float fx = (float)(xy & 0xFFFF) * 0.25f;
    float fy = (float)(xy >> 16)    * 0.25f;
    int x0 = (int)floorf(fx);
    int y0 = (int)floorf(fy);
    float wx = fx - (float)x0, wy = fy - (float)y0;
    int gx0 = x0 - 3, gy0 = y0 - 3;

    const float* base = fmap + (size_t)(b * CH + half * 64) * OH * OW;

    // 4 warps: lanes -> (yy,xx) of 8x4 sub-window; each warp loads 16 channels
    int warp = threadIdx.x >> 5, lane = threadIdx.x & 31;
    int yy = lane >> 3, xx = lane & 7;
    int gx = gx0 + xx;
    bool okx = (gx >= 0 && gx < OW);
    int gya = gy0 + yy;
    int gyb = gya + 4;
    bool oka = okx && (gya >= 0 && gya < OH);
    bool okb = okx && (gyb < OH);
    #pragma unroll 4
    for (int k = 0; k < 16; k++) {
        int c = warp * 16 + k;
        const float* img = base + (size_t)c * OH * OW;
        float va = oka ? __ldg(img + gya*OW + gx) : 0.f;
        float vb = okb ? __ldg(img + gyb*OW + gx) : 0.f;
        s[c * 65 + (yy*8 + xx)]     = va;
        s[c * 65 + ((yy+4)*8 + xx)] = vb;
    }
    __syncthreads();

    float w00 = (1.f - wx) * (1.f - wy);
    float w10 = wx * (1.f - wy);
    float w01 = (1.f - wx) * wy;
    float w11 = wx * wy;

    if (threadIdx.x < 64) {
        int c = threadIdx.x;
        float reg[64];
        #pragma unroll
        for (int k = 0; k < 64; k++) reg[k] = s[c * 65 + k];
        __syncthreads();

        #pragma unroll
        for (int j = 0; j < 7; j++) {
            #pragma unroll
            for (int i = 0; i < 7; i++) {
                float acc = reg[j*8 + i]       * w00
                          + reg[j*8 + i + 1]   * w10
                          + reg[(j+1)*8 + i]   * w01
                          + reg[(j+1)*8 + i+1] * w11;
                s[c * 49 + (j*7 + i)] = acc;
            }
        }
    } else {
        __syncthreads();
    }
    __syncthreads();

    float* o = out + (size_t)bp * (CH * 49) + half * (64 * 49);
    for (int k = threadIdx.x; k < 64 * 49; k += 128)
        o[k] = s[k];
}

// ================= K5: patches_c — on-the-fly imap conv =================
__global__ void k_patches_c(
    const float* __restrict__ frame,
    const float* __restrict__ wc,
    const float* __restrict__ bc,
    float* __restrict__ out)
{
    __shared__ float s_in[121];
    int bp = blockIdx.x;
    int b  = bp / NP;
    int c  = threadIdx.x;
    int xy = d_selxy[bp];
    float fx = (float)(xy & 0xFFFF) * 0.25f;
    float fy = (float)(xy >> 16)    * 0.25f;
    int x0 = (int)floorf(fx);
    int y0 = (int)floorf(fy);
    float wx = fx - (float)x0, wy = fy - (float)y0;

    const float* f = frame + (size_t)b * H * W;
    int row0 = y0 * 4 - 3, col0 = x0 * 4 - 3;
    for (int i = threadIdx.x; i < 121; i += 128) {
        int r = i / 11, cc = i - r * 11;
        int yyy = row0 + r, xxx = col0 + cc;
        s_in[i] = (yyy >= 0 && yyy < H && xxx >= 0 && xxx < W) ? f[yyy*W + xxx] : 0.f;
    }
    float wreg[49];
    #pragma unroll
    for (int i = 0; i < 49; i++) wreg[i] = __ldg(wc + c*49 + i);
    float bias = __ldg(bc + c);
    __syncthreads();

    float wts[4] = { (1.f-wx)*(1.f-wy), wx*(1.f-wy), (1.f-wx)*wy, wx*wy };
    float acc = 0.f;
    #pragma unroll
    for (int n = 0; n < 4; n++) {
        int dxn = n & 1, dyn = n >> 1;
        int xi = x0 + dxn, yi = y0 + dyn;
        if (xi < OW && yi < OH) {
            float v = bias;
            #pragma unroll
            for (int ky = 0; ky < 7; ky++)
                #pragma unroll
                for (int kx = 0; kx < 7; kx++)
                    v = fmaf(s_in[(dyn*4 + ky)*11 + (dxn*4 + kx)], wreg[ky*7 + kx], v);
            v = fmaxf(v, 0.f);
            acc += v * wts[n];
        }
    }
    out[(size_t)bp * CH + c] = acc;
}

// ---------------- launch: fork-join across two streams ---------------------------
extern "C" void kernel_launch(void* const* d_in, const int* in_sizes, int n_in,
                              void* d_out, int out_size) {
    const float* frame = (const float*)d_in[0];
    const float* w_f   = (const float*)d_in[1];
    const float* b_f   = (const float*)d_in[2];
    const float* w_c   = (const float*)d_in[3];
    const float* b_c   = (const float*)d_in[4];

    float* out        = (float*)d_out;
    float* out_coords = out;                                   // 8*192*2
    float* out_pf     = out + 3072;                            // 8*192*128*49
    float* out_pc     = out + 3072 + 9633792;                  // 8*192*128
    float* out_fmap   = out + 3072 + 9633792 + 196608;         // 8*128*120*160

    static cudaStream_t s1 = 0;
    static cudaEvent_t e_fork = 0, e_topk = 0, e_side = 0;
    if (!s1) {
        cudaStreamCreateWithFlags(&s1, cudaStreamNonBlocking);
        cudaEventCreateWithFlags(&e_fork, cudaEventDisableTiming);
        cudaEventCreateWithFlags(&e_topk, cudaEventDisableTiming);
        cudaEventCreateWithFlags(&e_side, cudaEventDisableTiming);
    }

    // fork
    cudaEventRecord(e_fork, 0);
    cudaStreamWaitEvent(s1, e_fork, 0);

    // side stream: harris -> topk -> patches_c
    k_harris<<<BN*256, 256, 0, s1>>>(frame);
    k_topk  <<<BN, 256, 0, s1>>>(out_coords);
    cudaEventRecord(e_topk, s1);
    k_patches_c<<<BN*NP, 128, 0, s1>>>(frame, w_c, b_c, out_pc);
    cudaEventRecord(e_side, s1);

    // main stream: conv, then patches_f (needs conv output AND topk coords)
    dim3 gconv(OW/32, OH/2, BN);
    k_conv<<<gconv, 64>>>(frame, w_f, b_f, out_fmap);
    cudaStreamWaitEvent(0, e_topk, 0);
    k_patches_f<<<BN*NP*2, 128>>>(out_fmap, out_pf);

    // join
    cudaStreamWaitEvent(0, e_side, 0);
}